// round 7
// baseline (speedup 1.0000x reference)
#include <cuda_runtime.h>
#include <float.h>

#define N_COLS   32000
#define NV4      8000              // N_COLS/4
#define THREADS  256
#define NWARPS   8
#define CAP      40                // per-thread stash slots
#define MAX_ROWS 4096
#define BITERS   26

__device__ float g_row_loss[MAX_ROWS];
__device__ unsigned g_done = 0;

__global__ void __launch_bounds__(THREADS, 4)
entmax15_fused(const float* __restrict__ inp, const int* __restrict__ tgt,
               float* __restrict__ out, int rows) {
    __shared__ float stash[CAP][THREADS];    // 40 KB, conflict-free columns
    __shared__ float red[NWARPS];
    __shared__ float red3[3 * NWARPS];
    __shared__ int   ired[NWARPS];
    __shared__ int   s_last;

    const int row  = blockIdx.x;
    const int tid  = threadIdx.x;
    const int lane = tid & 31;
    const int w    = tid >> 5;
    const float* rp = inp + (size_t)row * N_COLS;
    const float4* g4 = (const float4*)rp;

    // ---- Phase A: threshold estimate = block max of first 1024 elements ----
    float4 v0 = g4[tid];
    float e = fmaxf(fmaxf(v0.x, v0.y), fmaxf(v0.z, v0.w));
    #pragma unroll
    for (int o = 16; o; o >>= 1) e = fmaxf(e, __shfl_xor_sync(0xffffffffu, e, o));
    if (lane == 0) red[w] = e;
    __syncthreads();
    float m0 = red[0];
    #pragma unroll
    for (int k = 1; k < NWARPS; ++k) m0 = fmaxf(m0, red[k]);
    __syncthreads();
    const float thr = m0 - 2.0f;   // safe: m0 <= m  =>  keeps every true candidate

    // ---- Single DRAM pass: per-thread straight-line filter, NO cross-lane ops ----
    float lmax = m0;
    int   cnt  = 0;
    #pragma unroll 4
    for (int p = 0; p < 31; ++p) {
        float4 v = g4[p * THREADS + tid];
        float xs[4] = {v.x, v.y, v.z, v.w};
        #pragma unroll
        for (int c = 0; c < 4; ++c) {
            lmax = fmaxf(lmax, xs[c]);
            if (xs[c] >= thr) {
                if (cnt < CAP) stash[cnt][tid] = xs[c];
                cnt++;
            }
        }
    }
    if (tid < 64) {                        // tail: elements [31744, 32000)
        float4 v = g4[31 * THREADS + tid];
        float xs[4] = {v.x, v.y, v.z, v.w};
        #pragma unroll
        for (int c = 0; c < 4; ++c) {
            lmax = fmaxf(lmax, xs[c]);
            if (xs[c] >= thr) {
                if (cnt < CAP) stash[cnt][tid] = xs[c];
                cnt++;
            }
        }
    }

    // ---- Exact block max + overflow flag ----
    float wm = lmax;
    #pragma unroll
    for (int o = 16; o; o >>= 1) wm = fmaxf(wm, __shfl_xor_sync(0xffffffffu, wm, o));
    unsigned ob = __ballot_sync(0xffffffffu, cnt > CAP);
    if (lane == 0) { red[w] = wm; ired[w] = (ob != 0u); }
    __syncthreads();
    float m = red[0];
    int ovf = ired[0];
    #pragma unroll
    for (int k = 1; k < NWARPS; ++k) { m = fmaxf(m, red[k]); ovf |= ired[k]; }

    const int tii = tgt[row];
    const float tg_logit = __ldg(rp + ((tii < 0) ? 0 : (tii >= N_COLS ? N_COLS - 1 : tii)));

    if (!ovf) {
        // ---- Prune to true support in X-units: X=(v-m)/2 >= -1 ----
        int k2 = 0;
        const int cc = (cnt < CAP) ? cnt : CAP;
        for (int j = 0; j < cc; ++j) {
            float x = (stash[j][tid] - m) * 0.5f;
            if (x >= -1.0f) { stash[k2][tid] = x; k2++; }
        }
        cnt = k2;   // typically 0-2 per thread

        // ---- Block-wide bisection for tau in [-1, 0] ----
        float lo = -1.0f, hi = 0.0f;
        for (int it = 0; it < BITERS; ++it) {
            float mid = 0.5f * (lo + hi);
            float s = 0.0f;
            for (int j = 0; j < cnt; ++j) {
                float d = stash[j][tid] - mid;
                if (d > 0.0f) s = fmaf(d, d, s);
            }
            #pragma unroll
            for (int o = 16; o; o >>= 1) s += __shfl_xor_sync(0xffffffffu, s, o);
            if (lane == 0) red[w] = s;
            __syncthreads();
            float tot = 0.0f;
            #pragma unroll
            for (int k = 0; k < NWARPS; ++k) tot += red[k];
            __syncthreads();
            if (tot >= 1.0f) lo = mid; else hi = mid;   // uniform across block
        }
        const float tau = 0.5f * (lo + hi);

        // ---- Final sums ----
        float sp = 0.0f, s15 = 0.0f, spx = 0.0f;
        for (int j = 0; j < cnt; ++j) {
            float x = stash[j][tid], d = x - tau;
            if (d > 0.0f) { float p = d * d; sp += p; s15 = fmaf(p, d, s15); spx = fmaf(p, x, spx); }
        }
        #pragma unroll
        for (int o = 16; o; o >>= 1) {
            sp  += __shfl_xor_sync(0xffffffffu, sp,  o);
            s15 += __shfl_xor_sync(0xffffffffu, s15, o);
            spx += __shfl_xor_sync(0xffffffffu, spx, o);
        }
        if (lane == 0) { red3[w] = sp; red3[NWARPS + w] = s15; red3[2 * NWARPS + w] = spx; }
        __syncthreads();
        if (tid == 0) {
            float SP = 0, S15 = 0, SPX = 0;
            #pragma unroll
            for (int k = 0; k < NWARPS; ++k) { SP += red3[k]; S15 += red3[NWARPS + k]; SPX += red3[2 * NWARPS + k]; }
            float omega = (1.0f - S15) * (4.0f / 3.0f);
            g_row_loss[row] = omega + 2.0f * SPX + m * SP - tg_logit;
        }
    } else {
        // ---- Fallback (never expected): block bisection over GMEM row ----
        float lo = -1.0f, hi = 0.0f;
        for (int it = 0; it < BITERS; ++it) {
            float mid = 0.5f * (lo + hi);
            float s = 0.0f;
            for (int q = tid; q < NV4; q += THREADS) {
                float4 v = g4[q];
                float xs[4] = {v.x, v.y, v.z, v.w};
                #pragma unroll
                for (int c = 0; c < 4; ++c) {
                    float d = (xs[c] - m) * 0.5f - mid;
                    if (d > 0.0f) s = fmaf(d, d, s);
                }
            }
            #pragma unroll
            for (int o = 16; o; o >>= 1) s += __shfl_xor_sync(0xffffffffu, s, o);
            if (lane == 0) red[w] = s;
            __syncthreads();
            float tot = 0.0f;
            #pragma unroll
            for (int k = 0; k < NWARPS; ++k) tot += red[k];
            __syncthreads();
            if (tot >= 1.0f) lo = mid; else hi = mid;
        }
        const float tau = 0.5f * (lo + hi);
        float sp = 0.0f, s15 = 0.0f, spx = 0.0f;
        for (int q = tid; q < NV4; q += THREADS) {
            float4 v = g4[q];
            float xs[4] = {v.x, v.y, v.z, v.w};
            #pragma unroll
            for (int c = 0; c < 4; ++c) {
                float x = (xs[c] - m) * 0.5f, d = x - tau;
                if (d > 0.0f) { float p = d * d; sp += p; s15 = fmaf(p, d, s15); spx = fmaf(p, x, spx); }
            }
        }
        #pragma unroll
        for (int o = 16; o; o >>= 1) {
            sp  += __shfl_xor_sync(0xffffffffu, sp,  o);
            s15 += __shfl_xor_sync(0xffffffffu, s15, o);
            spx += __shfl_xor_sync(0xffffffffu, spx, o);
        }
        if (lane == 0) { red3[w] = sp; red3[NWARPS + w] = s15; red3[2 * NWARPS + w] = spx; }
        __syncthreads();
        if (tid == 0) {
            float SP = 0, S15 = 0, SPX = 0;
            #pragma unroll
            for (int k = 0; k < NWARPS; ++k) { SP += red3[k]; S15 += red3[NWARPS + k]; SPX += red3[2 * NWARPS + k]; }
            float omega = (1.0f - S15) * (4.0f / 3.0f);
            g_row_loss[row] = omega + 2.0f * SPX + m * SP - tg_logit;
        }
    }

    // ---- Completion protocol: last block computes the mean (deterministic) ----
    if (tid == 0) {
        __threadfence();
        unsigned old = atomicAdd(&g_done, 1u);
        s_last = (old == (unsigned)gridDim.x - 1u);
    }
    __syncthreads();
    if (s_last) {
        __threadfence();
        __shared__ float sred[THREADS];
        float v = 0.0f;
        for (int i = tid; i < rows; i += THREADS) v += g_row_loss[i];  // fixed order
        sred[tid] = v;
        __syncthreads();
        #pragma unroll
        for (int st = THREADS / 2; st; st >>= 1) {
            if (tid < st) sred[tid] += sred[tid + st];
            __syncthreads();
        }
        if (tid == 0) {
            out[0] = sred[0] / (float)rows;
            g_done = 0;   // reset for next graph replay
        }
    }
}

extern "C" void kernel_launch(void* const* d_in, const int* in_sizes, int n_in,
                              void* d_out, int out_size) {
    const float* inp = (const float*)d_in[0];
    const int*   tgt = (const int*)d_in[1];
    float*       out = (float*)d_out;
    const int rows = in_sizes[1];  // 4096

    entmax15_fused<<<rows, THREADS>>>(inp, tgt, out, rows);
}

// round 8
// speedup vs baseline: 1.4094x; 1.4094x over previous
#include <cuda_runtime.h>
#include <float.h>

#define N_COLS   32000
#define NV4      8000              // N_COLS/4
#define THREADS  256
#define NWARPS   8
#define FULLIT   31                // 31*256 = 7936 float4; tail 64 handled separately
#define TAILT    64
#define PHASEA   12                // phase-A sample: 12*256*4 = 12288 elements
#define CAP      32                // per-thread group-index slots (power of 2)
#define SEGCAP   192               // per-warp extracted-candidate capacity
#define NR       6                 // SEGCAP/32
#define NEWTON   10
#define MAX_ROWS 4096

__device__ float g_row_loss[MAX_ROWS];
__device__ unsigned g_done = 0;

__global__ void __launch_bounds__(THREADS)
entmax15_fused(const float* __restrict__ inp, const int* __restrict__ tgt,
               float* __restrict__ out, int rows) {
    __shared__ unsigned char idxs[CAP * THREADS];   // 8 KB: slot*256 + tid
    __shared__ float scal[NWARPS][SEGCAP];          // 6 KB
    __shared__ float red[NWARPS], red2[NWARPS];
    __shared__ float red3[3 * NWARPS];
    __shared__ int   ired[NWARPS];
    __shared__ int   s_last;

    const int row  = blockIdx.x;
    const int tid  = threadIdx.x;
    const int lane = tid & 31;
    const int w    = tid >> 5;
    const float* rp = inp + (size_t)row * N_COLS;
    const float4* g4 = (const float4*)rp;

    // ---- Phase A: threshold estimate = block max of first 12288 elements ----
    float e = -FLT_MAX;
    #pragma unroll
    for (int q = 0; q < PHASEA; ++q) {
        float4 v = g4[q * THREADS + tid];
        e = fmaxf(e, fmaxf(fmaxf(v.x, v.y), fmaxf(v.z, v.w)));
    }
    #pragma unroll
    for (int o = 16; o; o >>= 1) e = fmaxf(e, __shfl_xor_sync(0xffffffffu, e, o));
    if (lane == 0) red[w] = e;
    __syncthreads();
    float m0 = red[0];
    #pragma unroll
    for (int k = 1; k < NWARPS; ++k) m0 = fmaxf(m0, red[k]);
    __syncthreads();
    const float thr = m0 - 2.0f;   // safe: m0 <= m, so every true candidate's group passes

    // ---- Hot loop: group filter, branch-free 1-byte index stash ----
    // Unconditional wrap-masked store; slot cnt is overwritten until an accept
    // lands there, then cnt advances. Overflow (cnt > CAP) -> fallback.
    int cnt = 0;
    #pragma unroll 4
    for (int p = 0; p < FULLIT; ++p) {
        float4 v = g4[p * THREADS + tid];
        float gm = fmaxf(fmaxf(v.x, v.y), fmaxf(v.z, v.w));
        idxs[((cnt & (CAP - 1)) << 8) + tid] = (unsigned char)p;
        cnt += (gm >= thr);
    }
    if (tid < TAILT) {             // elements [31744, 32000)
        float4 v = g4[FULLIT * THREADS + tid];
        float gm = fmaxf(fmaxf(v.x, v.y), fmaxf(v.z, v.w));
        idxs[((cnt & (CAP - 1)) << 8) + tid] = (unsigned char)FULLIT;
        cnt += (gm >= thr);
    }

    unsigned ob = __ballot_sync(0xffffffffu, cnt > CAP);
    if (lane == 0) ired[w] = (ob != 0u);
    __syncthreads();
    int ovf = 0;
    #pragma unroll
    for (int k = 0; k < NWARPS; ++k) ovf |= ired[k];
    __syncthreads();

    const int tii = tgt[row];
    const float tg_logit = __ldg(rp + ((tii < 0) ? 0 : (tii >= N_COLS ? N_COLS - 1 : tii)));

    float m = m0;
    int mypos = 0;

    if (!ovf) {
        // ---- Exact row max from accepted groups (max's group always accepted) ----
        float lm = m0;
        const int cc = (cnt < CAP) ? cnt : CAP;
        for (int j = 0; j < cc; ++j) {
            int p = idxs[(j << 8) + tid];
            float4 v = g4[p * THREADS + tid];        // L1/L2-hot re-fetch
            lm = fmaxf(lm, fmaxf(fmaxf(v.x, v.y), fmaxf(v.z, v.w)));
        }
        #pragma unroll
        for (int o = 16; o; o >>= 1) lm = fmaxf(lm, __shfl_xor_sync(0xffffffffu, lm, o));
        if (lane == 0) red[w] = lm;
        __syncthreads();
        m = red[0];
        #pragma unroll
        for (int k = 1; k < NWARPS; ++k) m = fmaxf(m, red[k]);
        __syncthreads();

        // ---- Extract true candidates X=(v-m)/2 >= -1 into per-warp segment ----
        int wc = cc;
        #pragma unroll
        for (int o = 16; o; o >>= 1) { int t = __shfl_xor_sync(0xffffffffu, wc, o); wc = (t > wc) ? t : wc; }
        const unsigned lmask = (1u << lane) - 1u;
        for (int j = 0; j < wc; ++j) {
            bool valid = (j < cc);
            int p = valid ? idxs[(j << 8) + tid] : 0;
            float4 v = g4[p * THREADS + tid];
            float xs[4] = {v.x, v.y, v.z, v.w};
            #pragma unroll
            for (int c = 0; c < 4; ++c) {
                float x = (xs[c] - m) * 0.5f;
                bool keep = valid && (x >= -1.0f);
                unsigned b = __ballot_sync(0xffffffffu, keep);
                if (keep) {
                    int pos = mypos + __popc(b & lmask);
                    if (pos < SEGCAP) scal[w][pos] = x;
                }
                mypos += __popc(b);   // uniform across warp
            }
        }
        if (lane == 0) ired[w] = (mypos > SEGCAP);
        __syncthreads();
        int ovf2 = 0;
        #pragma unroll
        for (int k = 0; k < NWARPS; ++k) ovf2 |= ired[k];
        __syncthreads();
        ovf = ovf2;
    }

    if (!ovf) {
        // ---- Register-cache candidates; sentinel -2 contributes exactly 0 ----
        const int np = (mypos < SEGCAP) ? mypos : SEGCAP;
        float xr[NR];
        #pragma unroll
        for (int j = 0; j < NR; ++j) {
            int i = lane + j * 32;
            xr[j] = (i < np) ? scal[w][i] : -2.0f;
        }

        // ---- Newton on f(tau) = sum (x-tau)_+^2 - 1 (convex, from tau=-1) ----
        float tau = -1.0f;
        for (int it = 0; it < NEWTON; ++it) {
            float s1 = 0.0f, s2 = 0.0f;
            #pragma unroll
            for (int j = 0; j < NR; ++j) {
                float d = fmaxf(xr[j] - tau, 0.0f);
                s1 += d; s2 = fmaf(d, d, s2);
            }
            #pragma unroll
            for (int o = 16; o; o >>= 1) {
                s1 += __shfl_xor_sync(0xffffffffu, s1, o);
                s2 += __shfl_xor_sync(0xffffffffu, s2, o);
            }
            if (lane == 0) { red[w] = s1; red2[w] = s2; }
            __syncthreads();
            float S1 = 0.0f, S2 = 0.0f;
            #pragma unroll
            for (int k = 0; k < NWARPS; ++k) { S1 += red[k]; S2 += red2[k]; }
            __syncthreads();
            tau += (S2 - 1.0f) / (2.0f * S1);   // identical in every thread
        }

        // ---- Final sums ----
        float sp = 0.0f, s15 = 0.0f, spx = 0.0f;
        #pragma unroll
        for (int j = 0; j < NR; ++j) {
            float x = xr[j];
            float d = fmaxf(x - tau, 0.0f);
            float p = d * d;
            sp += p; s15 = fmaf(p, d, s15); spx = fmaf(p, x, spx);
        }
        #pragma unroll
        for (int o = 16; o; o >>= 1) {
            sp  += __shfl_xor_sync(0xffffffffu, sp,  o);
            s15 += __shfl_xor_sync(0xffffffffu, s15, o);
            spx += __shfl_xor_sync(0xffffffffu, spx, o);
        }
        if (lane == 0) { red3[w] = sp; red3[NWARPS + w] = s15; red3[2 * NWARPS + w] = spx; }
        __syncthreads();
        if (tid == 0) {
            float SP = 0, S15 = 0, SPX = 0;
            #pragma unroll
            for (int k = 0; k < NWARPS; ++k) { SP += red3[k]; S15 += red3[NWARPS + k]; SPX += red3[2 * NWARPS + k]; }
            float omega = (1.0f - S15) * (4.0f / 3.0f);
            g_row_loss[row] = omega + 2.0f * SPX + m * SP - tg_logit;
        }
    } else {
        // ---- Fallback (never expected): exact max + Newton over full row (L2) ----
        float lm = -FLT_MAX;
        for (int q = tid; q < NV4; q += THREADS) {
            float4 v = g4[q];
            lm = fmaxf(lm, fmaxf(fmaxf(v.x, v.y), fmaxf(v.z, v.w)));
        }
        #pragma unroll
        for (int o = 16; o; o >>= 1) lm = fmaxf(lm, __shfl_xor_sync(0xffffffffu, lm, o));
        if (lane == 0) red[w] = lm;
        __syncthreads();
        m = red[0];
        #pragma unroll
        for (int k = 1; k < NWARPS; ++k) m = fmaxf(m, red[k]);
        __syncthreads();

        float tau = -1.0f;
        for (int it = 0; it < 14; ++it) {
            float s1 = 0.0f, s2 = 0.0f;
            for (int q = tid; q < NV4; q += THREADS) {
                float4 v = g4[q];
                float xs[4] = {v.x, v.y, v.z, v.w};
                #pragma unroll
                for (int c = 0; c < 4; ++c) {
                    float d = fmaxf((xs[c] - m) * 0.5f - tau, 0.0f);
                    s1 += d; s2 = fmaf(d, d, s2);
                }
            }
            #pragma unroll
            for (int o = 16; o; o >>= 1) {
                s1 += __shfl_xor_sync(0xffffffffu, s1, o);
                s2 += __shfl_xor_sync(0xffffffffu, s2, o);
            }
            if (lane == 0) { red[w] = s1; red2[w] = s2; }
            __syncthreads();
            float S1 = 0.0f, S2 = 0.0f;
            #pragma unroll
            for (int k = 0; k < NWARPS; ++k) { S1 += red[k]; S2 += red2[k]; }
            __syncthreads();
            tau += (S2 - 1.0f) / (2.0f * S1);
        }

        float sp = 0.0f, s15 = 0.0f, spx = 0.0f;
        for (int q = tid; q < NV4; q += THREADS) {
            float4 v = g4[q];
            float xs[4] = {v.x, v.y, v.z, v.w};
            #pragma unroll
            for (int c = 0; c < 4; ++c) {
                float x = (xs[c] - m) * 0.5f;
                float d = fmaxf(x - tau, 0.0f);
                float p = d * d;
                sp += p; s15 = fmaf(p, d, s15); spx = fmaf(p, x, spx);
            }
        }
        #pragma unroll
        for (int o = 16; o; o >>= 1) {
            sp  += __shfl_xor_sync(0xffffffffu, sp,  o);
            s15 += __shfl_xor_sync(0xffffffffu, s15, o);
            spx += __shfl_xor_sync(0xffffffffu, spx, o);
        }
        if (lane == 0) { red3[w] = sp; red3[NWARPS + w] = s15; red3[2 * NWARPS + w] = spx; }
        __syncthreads();
        if (tid == 0) {
            float SP = 0, S15 = 0, SPX = 0;
            #pragma unroll
            for (int k = 0; k < NWARPS; ++k) { SP += red3[k]; S15 += red3[NWARPS + k]; SPX += red3[2 * NWARPS + k]; }
            float omega = (1.0f - S15) * (4.0f / 3.0f);
            g_row_loss[row] = omega + 2.0f * SPX + m * SP - tg_logit;
        }
    }

    // ---- Completion protocol: last block computes the mean (deterministic) ----
    if (tid == 0) {
        __threadfence();
        unsigned old = atomicAdd(&g_done, 1u);
        s_last = (old == (unsigned)gridDim.x - 1u);
    }
    __syncthreads();
    if (s_last) {
        __threadfence();
        __shared__ float sred[THREADS];
        float v = 0.0f;
        for (int i = tid; i < rows; i += THREADS) v += g_row_loss[i];  // fixed order
        sred[tid] = v;
        __syncthreads();
        #pragma unroll
        for (int st = THREADS / 2; st; st >>= 1) {
            if (tid < st) sred[tid] += sred[tid + st];
            __syncthreads();
        }
        if (tid == 0) {
            out[0] = sred[0] / (float)rows;
            g_done = 0;   // reset for next graph replay
        }
    }
}

extern "C" void kernel_launch(void* const* d_in, const int* in_sizes, int n_in,
                              void* d_out, int out_size) {
    const float* inp = (const float*)d_in[0];
    const int*   tgt = (const int*)d_in[1];
    float*       out = (float*)d_out;
    const int rows = in_sizes[1];  // 4096

    entmax15_fused<<<rows, THREADS>>>(inp, tgt, out, rows);
}